// round 1
// baseline (speedup 1.0000x reference)
#include <cuda_runtime.h>

#define BATCH 16

// Ping-pong activation buffers [16,32,32,32] fp32 (2 MB each) — static device
// globals per allocation rules.
__device__ float g_bufA[BATCH * 32 * 32 * 32];
__device__ float g_bufB[BATCH * 32 * 32 * 32];

// Iterated circular pad (31 iterations) index map, closed form.
// Core: j in [31,62] -> j-31.  Outside: even j -> 31, odd j -> 0.
// (Verified against the reference's iterated concat construction.)
__device__ __forceinline__ int padidx(int j) {
    return (j >= 31 && j <= 62) ? (j - 31) : ((j & 1) ? 0 : 31);
}

// One CTA computes out[b, 0..31 co, oy0..oy0+3, 0..31 ox]  (4096 outputs).
// Loop over ci: gather padded rows [8*oyq .. 8*oyq+37] x 94 cols into smem,
// then accumulate the k=32 s=2 cross-correlation.
// Threads (256): oy_l = t>>6 (4), co group = (t>>3)&7 (8 groups of 4 co),
// ox group = t&7 (8 groups of 4 ox). Per-thread register tile 4co x 4ox.
template <int NCI, bool RELU>
__global__ __launch_bounds__(256, 1)
void conv_kernel(const float* __restrict__ in,    // [B, NCI, 32, 32]
                 const float* __restrict__ w,     // [32, NCI, 32, 32]
                 const float* __restrict__ bias,  // [32]
                 float* __restrict__ out)         // [B, 32, 32, 32]
{
    __shared__ float s[38][96];

    const int b    = blockIdx.y;
    const int oyq  = blockIdx.x;        // 0..7
    const int t    = threadIdx.x;       // 0..255
    const int oy_l = t >> 6;            // 0..3
    const int co0  = ((t >> 3) & 7) * 4;
    const int ox0  = (t & 7) * 4;
    const int pr0  = oyq * 8;           // first padded row needed

    float acc[4][4] = {};

    for (int ci = 0; ci < NCI; ci++) {
        __syncthreads();
        const float* src = in + (b * NCI + ci) * 1024;
        // Gather padded slice: 38 rows x 94 cols = 3572 elements.
        for (int k = t; k < 38 * 94; k += 256) {
            int lr = k / 94;
            int c  = k - lr * 94;
            s[lr][c] = src[padidx(pr0 + lr) * 32 + padidx(c)];
        }
        __syncthreads();

        const float* wci = w + ci * 1024;
        for (int ky = 0; ky < 32; ky++) {
            const float* srow = &s[2 * oy_l + ky][2 * ox0];
            const float* wr   = wci + ky * 32;
            #pragma unroll
            for (int kx4 = 0; kx4 < 32; kx4 += 4) {
                const float4 wv0 = __ldg((const float4*)(wr + (co0 + 0) * (NCI * 1024) + kx4));
                const float4 wv1 = __ldg((const float4*)(wr + (co0 + 1) * (NCI * 1024) + kx4));
                const float4 wv2 = __ldg((const float4*)(wr + (co0 + 2) * (NCI * 1024) + kx4));
                const float4 wv3 = __ldg((const float4*)(wr + (co0 + 3) * (NCI * 1024) + kx4));
                #pragma unroll
                for (int q = 0; q < 4; q++) {
                    const int kx = kx4 + q;
                    const float i0 = srow[kx];
                    const float i1 = srow[kx + 2];
                    const float i2 = srow[kx + 4];
                    const float i3 = srow[kx + 6];
                    const float w0 = (q == 0) ? wv0.x : (q == 1) ? wv0.y : (q == 2) ? wv0.z : wv0.w;
                    const float w1 = (q == 0) ? wv1.x : (q == 1) ? wv1.y : (q == 2) ? wv1.z : wv1.w;
                    const float w2 = (q == 0) ? wv2.x : (q == 1) ? wv2.y : (q == 2) ? wv2.z : wv2.w;
                    const float w3 = (q == 0) ? wv3.x : (q == 1) ? wv3.y : (q == 2) ? wv3.z : wv3.w;
                    acc[0][0] = fmaf(w0, i0, acc[0][0]);
                    acc[0][1] = fmaf(w0, i1, acc[0][1]);
                    acc[0][2] = fmaf(w0, i2, acc[0][2]);
                    acc[0][3] = fmaf(w0, i3, acc[0][3]);
                    acc[1][0] = fmaf(w1, i0, acc[1][0]);
                    acc[1][1] = fmaf(w1, i1, acc[1][1]);
                    acc[1][2] = fmaf(w1, i2, acc[1][2]);
                    acc[1][3] = fmaf(w1, i3, acc[1][3]);
                    acc[2][0] = fmaf(w2, i0, acc[2][0]);
                    acc[2][1] = fmaf(w2, i1, acc[2][1]);
                    acc[2][2] = fmaf(w2, i2, acc[2][2]);
                    acc[2][3] = fmaf(w2, i3, acc[2][3]);
                    acc[3][0] = fmaf(w3, i0, acc[3][0]);
                    acc[3][1] = fmaf(w3, i1, acc[3][1]);
                    acc[3][2] = fmaf(w3, i2, acc[3][2]);
                    acc[3][3] = fmaf(w3, i3, acc[3][3]);
                }
            }
        }
    }

    const int oy = oyq * 4 + oy_l;
    #pragma unroll
    for (int i = 0; i < 4; i++) {
        const float bv = bias[co0 + i];
        float* orow = out + (b * 32 + co0 + i) * 1024 + oy * 32 + ox0;
        #pragma unroll
        for (int j = 0; j < 4; j++) {
            float v = acc[i][j] + bv;
            if (RELU) v = fmaxf(v, 0.0f);
            orow[j] = v;
        }
    }
}

// Final 1x1 conv: out[b,0,y,x] = sum_co h[b,co,y,x] * ow[co] + ob[0]
__global__ void out1x1_kernel(const float* __restrict__ h,
                              const float* __restrict__ ow,
                              const float* __restrict__ ob,
                              float* __restrict__ out)
{
    const int i = blockIdx.x * blockDim.x + threadIdx.x;
    if (i >= BATCH * 1024) return;
    const int b = i >> 10;
    const int p = i & 1023;
    const float* hp = h + b * 32 * 1024 + p;
    float acc = ob[0];
    #pragma unroll
    for (int co = 0; co < 32; co++)
        acc = fmaf(hp[co * 1024], __ldg(ow + co), acc);
    out[i] = acc;
}

extern "C" void kernel_launch(void* const* d_in, const int* in_sizes, int n_in,
                              void* d_out, int out_size)
{
    const float* x       = (const float*)d_in[0];
    const float* in_w    = (const float*)d_in[1];
    const float* in_b    = (const float*)d_in[2];
    const float* convs_w = (const float*)d_in[3];
    const float* convs_b = (const float*)d_in[4];
    const float* out_w   = (const float*)d_in[5];
    const float* out_b   = (const float*)d_in[6];

    float *gA = nullptr, *gB = nullptr;
    cudaGetSymbolAddress((void**)&gA, g_bufA);
    cudaGetSymbolAddress((void**)&gB, g_bufB);

    dim3 grid(8, BATCH);

    // in_conv: 1 input channel, no ReLU
    conv_kernel<1, false><<<grid, 256>>>(x, in_w, in_b, gA);

    // 20 hidden layers: 32 input channels, ReLU
    const float* cur = gA;
    float* nxt = gB;
    for (int l = 0; l < 20; l++) {
        conv_kernel<32, true><<<grid, 256>>>(
            cur, convs_w + (size_t)l * 32 * 32 * 1024, convs_b + l * 32, nxt);
        float* tmp = (float*)cur;
        cur = nxt;
        nxt = tmp;
    }

    // 1x1 output conv
    out1x1_kernel<<<(BATCH * 1024) / 256, 256>>>(cur, out_w, out_b, (float*)d_out);
}

// round 3
// speedup vs baseline: 3.4576x; 3.4576x over previous
#include <cuda_runtime.h>
#include <cuda_fp16.h>
#include <cstdint>

#define BATCH 16

// Ping-pong activation buffers [16,32,32,32] fp32.
__device__ float g_bufA[BATCH * 32 * 32 * 32];
__device__ float g_bufB[BATCH * 32 * 32 * 32];

// Converted weights (fp16 hi/lo split, lo pre-scaled by 2048):
// hidden: [20][ci 32][ky 32][h 2][co 32][kx 32], input layer appended.
#define WL_HALVES (32 * 32 * 2 * 32 * 32)     // 2,097,152 halves per hidden layer
#define WIN_OFF   (20 * WL_HALVES)
__device__ __half g_wcv[20 * WL_HALVES + 32 * 2 * 32 * 32];

// Iterated circular pad (31 iters): core [31,62]->j-31; outside: even->31, odd->0.
__device__ __forceinline__ int padidx(int j) {
    return (j >= 31 && j <= 62) ? (j - 31) : ((j & 1) ? 0 : 31);
}

// ---------------- weight conversion (runs every launch; deterministic) -------
__global__ void convert_weights(const float* __restrict__ convs_w,
                                const float* __restrict__ in_w)
{
    long long i = (long long)blockIdx.x * 256 + threadIdx.x;
    const long long NH = 20ll * 32 * 32 * 32 * 32;
    if (i < NH) {
        int kx = (int)(i & 31); long long r = i >> 5;
        int co = (int)(r & 31); r >>= 5;
        int ky = (int)(r & 31); r >>= 5;
        int ci = (int)(r & 31); r >>= 5;
        int l  = (int)r;
        float v = convs_w[((((long long)l * 32 + co) * 32 + ci) * 32 + ky) * 32 + kx];
        __half h  = __float2half_rn(v);
        __half lo = __float2half_rn((v - __half2float(h)) * 2048.0f);
        long long ob = (long long)l * WL_HALVES
                     + ((((long long)ci * 32 + ky) * 2 + 0) * 32 + co) * 32 + kx;
        g_wcv[ob] = h;
        g_wcv[ob + 32 * 32] = lo;          // h-dim stride = 1024 halves
    } else {
        long long j = i - NH;
        if (j < 32 * 32 * 32) {
            int kx = (int)(j & 31); int rr = (int)(j >> 5);
            int co = rr & 31; rr >>= 5;
            int ky = rr & 31;
            float v = in_w[(co * 32 + ky) * 32 + kx];   // [co][1][ky][kx]
            __half h  = __float2half_rn(v);
            __half lo = __float2half_rn((v - __half2float(h)) * 2048.0f);
            long long ob = WIN_OFF + (((long long)ky * 2 + 0) * 32 + co) * 32 + kx;
            g_wcv[ob] = h;
            g_wcv[ob + 32 * 32] = lo;
        }
    }
}

// ---------------- mma helper -------------------------------------------------
__device__ __forceinline__ void mma16816(float* d, const uint32_t* a,
                                         uint32_t b0, uint32_t b1) {
    asm volatile(
        "mma.sync.aligned.m16n8k16.row.col.f32.f16.f16.f32 "
        "{%0,%1,%2,%3}, {%4,%5,%6,%7}, {%8,%9}, {%0,%1,%2,%3};"
        : "+f"(d[0]), "+f"(d[1]), "+f"(d[2]), "+f"(d[3])
        : "r"(a[0]), "r"(a[1]), "r"(a[2]), "r"(a[3]), "r"(b0), "r"(b1));
}

// ---------------- smem layout (halves) ---------------------------------------
#define PH_H 0                       // pad hi [38][96]
#define PL_H 3648                    // pad lo [38][96]
#define SB_H 7296                    // B stage [2 buf][4 ky][2 h][32 co][40]
#define SMEM_HALVES (7296 + 20480)
#define SMEM_SZ (SMEM_HALVES * 2)

// One CTA: out[b, :, oyq*4 .. +3, :]. M=128, N=32, K=NCI*1024.
// Warp w: M-tile rows m = w*16..w*16+15  (oy_l = w>>1, ox = (w&1)*16 + r).
template <int NCI, bool RELU>
__global__ __launch_bounds__(256, 1)
void mma_conv(const float* __restrict__ in,     // [B, NCI, 32, 32]
              const __half* __restrict__ wv,    // converted [ci][ky][h][co][kx]
              const float* __restrict__ bias,   // [32]
              float* __restrict__ out)          // [B, 32, 32, 32]
{
    extern __shared__ __half sh[];
    __half* pH = sh + PH_H;
    __half* pL = sh + PL_H;
    __half* sB = sh + SB_H;

    const int b = blockIdx.y, oyq = blockIdx.x;
    const int t = threadIdx.x, lane = t & 31, wid = t >> 5;
    const int pr0 = oyq * 8;
    const int oy_l = wid >> 1, ox0 = (wid & 1) * 16;

    auto load_pad = [&](int ci) {
        const float* src = in + (b * NCI + ci) * 1024;
        for (int k = t; k < 38 * 94; k += 256) {
            int lr = k / 94, c = k - lr * 94;
            float v = src[padidx(pr0 + lr) * 32 + padidx(c)];
            __half h = __float2half_rn(v);
            pH[lr * 96 + c] = h;
            pL[lr * 96 + c] = __float2half_rn((v - __half2float(h)) * 2048.0f);
        }
    };

    // staging: thread t owns one (ky_l, h, co) row of 32 kx = 64B = 4 uint4
    const int st_ky = t >> 6, st_h = (t >> 5) & 1, st_co = t & 31;
    __half* st_dst0 = sB + ((st_ky * 2 + st_h) * 32 + st_co) * 40;

    constexpr int NCHUNK = NCI * 8;     // 4 ky per chunk

    uint4 pf[4];
    {
        const uint4* g = (const uint4*)wv + t * 4;
        pf[0] = g[0]; pf[1] = g[1]; pf[2] = g[2]; pf[3] = g[3];
    }
    load_pad(0);
    __syncthreads();

    float C1[16] = {}, C2[16] = {};
    const float* dummy = in;  (void)dummy;

    for (int c = 0; c < NCHUNK; c++) {
        const int buf = c & 1;

        if (NCI > 1 && c > 0 && (c & 7) == 0) {
            __syncthreads();            // all readers of old pad done
            load_pad(c >> 3);
        }

        // store chunk c into smem B buffer
        {
            uint4* d = (uint4*)(st_dst0 + buf * 10240);
            d[0] = pf[0]; d[1] = pf[1]; d[2] = pf[2]; d[3] = pf[3];
        }
        // prefetch chunk c+1
        if (c + 1 < NCHUNK) {
            const uint4* g = (const uint4*)wv + (c + 1) * 1024 + t * 4;
            pf[0] = g[0]; pf[1] = g[1]; pf[2] = g[2]; pf[3] = g[3];
        }
        __syncthreads();

        const int ky0 = (c & 7) * 4;
        #pragma unroll
        for (int kyl = 0; kyl < 4; kyl++) {
            const int R = 2 * oy_l + ky0 + kyl;
            const __half* arow = pH + R * 96 + 2 * ox0;
            const __half* lrow = pL + R * 96 + 2 * ox0;
            #pragma unroll
            for (int kxi = 0; kxi < 2; kxi++) {
                const int kxh  = kxi * 16;
                const int aoff = kxh + 2 * (lane >> 2) + 2 * (lane & 3);
                uint32_t ah[4], al[4];
                ah[0] = *(const uint32_t*)(arow + aoff);
                ah[1] = *(const uint32_t*)(arow + aoff + 16);
                ah[2] = *(const uint32_t*)(arow + aoff + 8);
                ah[3] = *(const uint32_t*)(arow + aoff + 24);
                al[0] = *(const uint32_t*)(lrow + aoff);
                al[1] = *(const uint32_t*)(lrow + aoff + 16);
                al[2] = *(const uint32_t*)(lrow + aoff + 8);
                al[3] = *(const uint32_t*)(lrow + aoff + 24);
                const __half* bbase = sB + buf * 10240 + kyl * 2560;  // h=0
                const int bo = kxh + (lane & 3) * 2 + (lane >> 2) * 40;
                #pragma unroll
                for (int nt = 0; nt < 4; nt++) {
                    const __half* bp = bbase + nt * 8 * 40 + bo;
                    uint32_t bh0 = *(const uint32_t*)(bp);
                    uint32_t bh1 = *(const uint32_t*)(bp + 8);
                    uint32_t bl0 = *(const uint32_t*)(bp + 1280);
                    uint32_t bl1 = *(const uint32_t*)(bp + 1288);
                    mma16816(C1 + nt * 4, ah, bh0, bh1);
                    mma16816(C2 + nt * 4, al, bh0, bh1);
                    mma16816(C2 + nt * 4, ah, bl0, bl1);
                }
            }
        }
    }

    // epilogue
    const int oy = oyq * 4 + oy_l;
    const int r  = lane >> 2;
    const float inv = 1.0f / 2048.0f;
    #pragma unroll
    for (int nt = 0; nt < 4; nt++) {
        const int co = nt * 8 + (lane & 3) * 2;
        const float b0v = bias[co], b1v = bias[co + 1];
        float v00 = C1[nt * 4 + 0] + C2[nt * 4 + 0] * inv + b0v;
        float v01 = C1[nt * 4 + 1] + C2[nt * 4 + 1] * inv + b1v;
        float v10 = C1[nt * 4 + 2] + C2[nt * 4 + 2] * inv + b0v;
        float v11 = C1[nt * 4 + 3] + C2[nt * 4 + 3] * inv + b1v;
        if (RELU) {
            v00 = fmaxf(v00, 0.f); v01 = fmaxf(v01, 0.f);
            v10 = fmaxf(v10, 0.f); v11 = fmaxf(v11, 0.f);
        }
        const int oxa = ox0 + r, oxb = oxa + 8;
        out[((b * 32 + co    ) * 32 + oy) * 32 + oxa] = v00;
        out[((b * 32 + co + 1) * 32 + oy) * 32 + oxa] = v01;
        out[((b * 32 + co    ) * 32 + oy) * 32 + oxb] = v10;
        out[((b * 32 + co + 1) * 32 + oy) * 32 + oxb] = v11;
    }
}

// Final 1x1 conv
__global__ void out1x1_kernel(const float* __restrict__ h,
                              const float* __restrict__ ow,
                              const float* __restrict__ ob,
                              float* __restrict__ out)
{
    const int i = blockIdx.x * blockDim.x + threadIdx.x;
    if (i >= BATCH * 1024) return;
    const int b = i >> 10;
    const int p = i & 1023;
    const float* hp = h + b * 32 * 1024 + p;
    float acc = ob[0];
    #pragma unroll
    for (int co = 0; co < 32; co++)
        acc = fmaf(hp[co * 1024], __ldg(ow + co), acc);
    out[i] = acc;
}

extern "C" void kernel_launch(void* const* d_in, const int* in_sizes, int n_in,
                              void* d_out, int out_size)
{
    const float* x       = (const float*)d_in[0];
    const float* in_w    = (const float*)d_in[1];
    const float* in_b    = (const float*)d_in[2];
    const float* convs_w = (const float*)d_in[3];
    const float* convs_b = (const float*)d_in[4];
    const float* out_w   = (const float*)d_in[5];
    const float* out_b   = (const float*)d_in[6];

    float *gA = nullptr, *gB = nullptr;
    __half* wcv = nullptr;
    cudaGetSymbolAddress((void**)&gA, g_bufA);
    cudaGetSymbolAddress((void**)&gB, g_bufB);
    cudaGetSymbolAddress((void**)&wcv, g_wcv);

    // convert all weights to split-fp16 layout
    const long long total = 20ll * 32 * 32 * 32 * 32 + 32 * 32 * 32;
    convert_weights<<<(int)((total + 255) / 256), 256>>>(convs_w, in_w);

    cudaFuncSetAttribute(mma_conv<1, false>,
                         cudaFuncAttributeMaxDynamicSharedMemorySize, SMEM_SZ);
    cudaFuncSetAttribute(mma_conv<32, true>,
                         cudaFuncAttributeMaxDynamicSharedMemorySize, SMEM_SZ);

    dim3 grid(8, BATCH);

    mma_conv<1, false><<<grid, 256, SMEM_SZ>>>(x, wcv + WIN_OFF, in_b, gA);

    const float* cur = gA;
    float* nxt = gB;
    for (int l = 0; l < 20; l++) {
        mma_conv<32, true><<<grid, 256, SMEM_SZ>>>(
            cur, wcv + (size_t)l * WL_HALVES, convs_b + l * 32, nxt);
        float* tmp = (float*)cur;
        cur = nxt;
        nxt = tmp;
    }

    out1x1_kernel<<<(BATCH * 1024) / 256, 256>>>(cur, out_w, out_b, (float*)d_out);
}

// round 4
// speedup vs baseline: 3.6272x; 1.0490x over previous
#include <cuda_runtime.h>
#include <cuda_fp16.h>
#include <cstdint>

#define BATCH 16

// Ping-pong activation buffers [16,32,32,32] fp32.
__device__ float g_bufA[BATCH * 32 * 32 * 32];
__device__ float g_bufB[BATCH * 32 * 32 * 32];

// Converted weights (fp16 hi/lo split, lo pre-scaled by 2048), k-permuted:
// hidden: [20][ci 32][ky 32][h 2][co 32][kx 32], input layer appended.
#define WL_HALVES (32 * 32 * 2 * 32 * 32)
#define WIN_OFF   (20 * WL_HALVES)
__device__ __half g_wcv[20 * WL_HALVES + 32 * 2 * 32 * 32];

// Iterated circular pad (31 iters): core [31,62]->j-31; outside: even->31, odd->0.
__device__ __forceinline__ int padidx(int j) {
    return (j >= 31 && j <= 62) ? (j - 31) : ((j & 1) ? 0 : 31);
}

// k-permutation: pos holds kx such that halves {2q,2q+1,2q+8,2q+9} are
// contiguous (one LDS.64 -> b0,b1 fragment regs).
__device__ __forceinline__ int kperm(int kx) {
    return (kx & 16) + 4 * ((kx & 7) >> 1) + ((kx >> 3) & 1) * 2 + (kx & 1);
}

// ---------------- weight conversion --------------------------------------
__global__ void convert_weights(const float* __restrict__ convs_w,
                                const float* __restrict__ in_w)
{
    long long i = (long long)blockIdx.x * 256 + threadIdx.x;
    const long long NH = 20ll * 32 * 32 * 32 * 32;
    if (i < NH) {
        int kx = (int)(i & 31); long long r = i >> 5;
        int co = (int)(r & 31); r >>= 5;
        int ky = (int)(r & 31); r >>= 5;
        int ci = (int)(r & 31); r >>= 5;
        int l  = (int)r;
        float v = convs_w[((((long long)l * 32 + co) * 32 + ci) * 32 + ky) * 32 + kx];
        __half h  = __float2half_rn(v);
        __half lo = __float2half_rn((v - __half2float(h)) * 2048.0f);
        long long ob = (long long)l * WL_HALVES
                     + ((((long long)ci * 32 + ky) * 2 + 0) * 32 + co) * 32 + kperm(kx);
        g_wcv[ob] = h;
        g_wcv[ob + 32 * 32] = lo;          // h-dim stride = 1024 halves
    } else {
        long long j = i - NH;
        if (j < 32 * 32 * 32) {
            int kx = (int)(j & 31); int rr = (int)(j >> 5);
            int co = rr & 31; rr >>= 5;
            int ky = rr & 31;
            float v = in_w[(co * 32 + ky) * 32 + kx];   // [co][1][ky][kx]
            __half h  = __float2half_rn(v);
            __half lo = __float2half_rn((v - __half2float(h)) * 2048.0f);
            long long ob = WIN_OFF + (((long long)ky * 2 + 0) * 32 + co) * 32 + kperm(kx);
            g_wcv[ob] = h;
            g_wcv[ob + 32 * 32] = lo;
        }
    }
}

// ---------------- mma helper ----------------------------------------------
__device__ __forceinline__ void mma16816(float* d, const uint32_t* a,
                                         uint32_t b0, uint32_t b1) {
    asm volatile(
        "mma.sync.aligned.m16n8k16.row.col.f32.f16.f16.f32 "
        "{%0,%1,%2,%3}, {%4,%5,%6,%7}, {%8,%9}, {%0,%1,%2,%3};"
        : "+f"(d[0]), "+f"(d[1]), "+f"(d[2]), "+f"(d[3])
        : "r"(a[0]), "r"(a[1]), "r"(a[2]), "r"(a[3]), "r"(b0), "r"(b1));
}

// ---------------- smem layout (halves) -------------------------------------
#define PH_H 0                        // pad hi [38][96]
#define PL_H 3648                     // pad lo [38][96]
#define SB_H 7296                     // B stage [2 buf][4 ky][2 h][32 co][48]
#define BUF_STRIDE 12288              // halves per B buffer
#define SMEM_HALVES (7296 + 2 * BUF_STRIDE)
#define SMEM_SZ (SMEM_HALVES * 2)

// One CTA: out[b, :, oyq*4 .. +3, :]. M=128, N=32, K=NCI*1024.
template <int NCI, bool RELU>
__global__ __launch_bounds__(256, 1)
void mma_conv(const float* __restrict__ in,     // [B, NCI, 32, 32]
              const __half* __restrict__ wv,    // converted weights
              const float* __restrict__ bias,   // [32]
              float* __restrict__ out)          // [B, 32, 32, 32]
{
    extern __shared__ __half sh[];
    __half* pH = sh + PH_H;
    __half* pL = sh + PL_H;
    __half* sB = sh + SB_H;

    const int b = blockIdx.y, oyq = blockIdx.x;
    const int t = threadIdx.x, lane = t & 31, wid = t >> 5;
    const int pr0 = oyq * 8;
    const int oy_l = wid >> 1, ox0 = (wid & 1) * 16;

    auto load_pad = [&](int ci) {
        const float* src = in + (b * NCI + ci) * 1024;
        for (int k = t; k < 38 * 94; k += 256) {
            int lr = k / 94, c = k - lr * 94;
            float v = src[padidx(pr0 + lr) * 32 + padidx(c)];
            __half h = __float2half_rn(v);
            pH[lr * 96 + c] = h;
            pL[lr * 96 + c] = __float2half_rn((v - __half2float(h)) * 2048.0f);
        }
    };

    // staging: thread t owns one (ky_l, h, co) row of 32 halves (48 stride)
    const int st_ky = t >> 6, st_h = (t >> 5) & 1, st_co = t & 31;
    __half* st_dst0 = sB + ((st_ky * 2 + st_h) * 32 + st_co) * 48;

    constexpr int NCHUNK = NCI * 8;     // 4 ky per chunk

    uint4 pf[4];
    {
        const uint4* g = (const uint4*)wv + t * 4;
        pf[0] = g[0]; pf[1] = g[1]; pf[2] = g[2]; pf[3] = g[3];
    }
    load_pad(0);
    __syncthreads();

    float C1[16] = {}, C2a[16] = {}, C2b[16] = {};

    // per-lane constant offsets
    const int g4 = lane >> 2, q4 = lane & 3;

    for (int c = 0; c < NCHUNK; c++) {
        const int buf = c & 1;

        if (NCI > 1 && c > 0 && (c & 7) == 0) {
            __syncthreads();
            load_pad(c >> 3);
        }

        {
            uint4* d = (uint4*)(st_dst0 + buf * BUF_STRIDE);
            d[0] = pf[0]; d[1] = pf[1]; d[2] = pf[2]; d[3] = pf[3];
        }
        if (c + 1 < NCHUNK) {
            const uint4* g = (const uint4*)wv + (c + 1) * 1024 + t * 4;
            pf[0] = g[0]; pf[1] = g[1]; pf[2] = g[2]; pf[3] = g[3];
        }
        __syncthreads();

        const int ky0 = (c & 7) * 4;
        #pragma unroll
        for (int kyl = 0; kyl < 4; kyl++) {
            const int R = 2 * oy_l + ky0 + kyl;
            const __half* arow = pH + R * 96 + 2 * ox0;
            const __half* lrow = pL + R * 96 + 2 * ox0;
            const __half* bky  = sB + buf * BUF_STRIDE + kyl * 3072
                               + g4 * 48 + q4 * 4;
            #pragma unroll
            for (int kxi = 0; kxi < 2; kxi++) {
                const int kxh  = kxi * 16;
                const int aoff = kxh + 2 * g4 + 2 * q4;
                uint32_t ah[4], al[4];
                ah[0] = *(const uint32_t*)(arow + aoff);
                ah[1] = *(const uint32_t*)(arow + aoff + 16);
                ah[2] = *(const uint32_t*)(arow + aoff + 8);
                ah[3] = *(const uint32_t*)(arow + aoff + 24);
                al[0] = *(const uint32_t*)(lrow + aoff);
                al[1] = *(const uint32_t*)(lrow + aoff + 16);
                al[2] = *(const uint32_t*)(lrow + aoff + 8);
                al[3] = *(const uint32_t*)(lrow + aoff + 24);

                const __half* bb = bky + kxh;
                uint2 bh[4], bl[4];
                #pragma unroll
                for (int nt = 0; nt < 4; nt++) {
                    bh[nt] = *(const uint2*)(bb + nt * 384);          // h=0
                    bl[nt] = *(const uint2*)(bb + nt * 384 + 1536);   // h=1
                }
                #pragma unroll
                for (int nt = 0; nt < 4; nt++)
                    mma16816(C1 + nt * 4, ah, bh[nt].x, bh[nt].y);
                #pragma unroll
                for (int nt = 0; nt < 4; nt++)
                    mma16816(C2a + nt * 4, al, bh[nt].x, bh[nt].y);
                #pragma unroll
                for (int nt = 0; nt < 4; nt++)
                    mma16816(C2b + nt * 4, ah, bl[nt].x, bl[nt].y);
            }
        }
    }

    // epilogue
    const int oy = oyq * 4 + oy_l;
    const int r  = lane >> 2;
    const float inv = 1.0f / 2048.0f;
    #pragma unroll
    for (int nt = 0; nt < 4; nt++) {
        const int co = nt * 8 + (lane & 3) * 2;
        const float b0v = bias[co], b1v = bias[co + 1];
        float v00 = C1[nt*4+0] + (C2a[nt*4+0] + C2b[nt*4+0]) * inv + b0v;
        float v01 = C1[nt*4+1] + (C2a[nt*4+1] + C2b[nt*4+1]) * inv + b1v;
        float v10 = C1[nt*4+2] + (C2a[nt*4+2] + C2b[nt*4+2]) * inv + b0v;
        float v11 = C1[nt*4+3] + (C2a[nt*4+3] + C2b[nt*4+3]) * inv + b1v;
        if (RELU) {
            v00 = fmaxf(v00, 0.f); v01 = fmaxf(v01, 0.f);
            v10 = fmaxf(v10, 0.f); v11 = fmaxf(v11, 0.f);
        }
        const int oxa = ox0 + r, oxb = oxa + 8;
        out[((b * 32 + co    ) * 32 + oy) * 32 + oxa] = v00;
        out[((b * 32 + co + 1) * 32 + oy) * 32 + oxa] = v01;
        out[((b * 32 + co    ) * 32 + oy) * 32 + oxb] = v10;
        out[((b * 32 + co + 1) * 32 + oy) * 32 + oxb] = v11;
    }
}

// Final 1x1 conv
__global__ void out1x1_kernel(const float* __restrict__ h,
                              const float* __restrict__ ow,
                              const float* __restrict__ ob,
                              float* __restrict__ out)
{
    const int i = blockIdx.x * blockDim.x + threadIdx.x;
    if (i >= BATCH * 1024) return;
    const int b = i >> 10;
    const int p = i & 1023;
    const float* hp = h + b * 32 * 1024 + p;
    float acc = ob[0];
    #pragma unroll
    for (int co = 0; co < 32; co++)
        acc = fmaf(hp[co * 1024], __ldg(ow + co), acc);
    out[i] = acc;
}

extern "C" void kernel_launch(void* const* d_in, const int* in_sizes, int n_in,
                              void* d_out, int out_size)
{
    const float* x       = (const float*)d_in[0];
    const float* in_w    = (const float*)d_in[1];
    const float* in_b    = (const float*)d_in[2];
    const float* convs_w = (const float*)d_in[3];
    const float* convs_b = (const float*)d_in[4];
    const float* out_w   = (const float*)d_in[5];
    const float* out_b   = (const float*)d_in[6];

    float *gA = nullptr, *gB = nullptr;
    __half* wcv = nullptr;
    cudaGetSymbolAddress((void**)&gA, g_bufA);
    cudaGetSymbolAddress((void**)&gB, g_bufB);
    cudaGetSymbolAddress((void**)&wcv, g_wcv);

    const long long total = 20ll * 32 * 32 * 32 * 32 + 32 * 32 * 32;
    convert_weights<<<(int)((total + 255) / 256), 256>>>(convs_w, in_w);

    cudaFuncSetAttribute(mma_conv<1, false>,
                         cudaFuncAttributeMaxDynamicSharedMemorySize, SMEM_SZ);
    cudaFuncSetAttribute(mma_conv<32, true>,
                         cudaFuncAttributeMaxDynamicSharedMemorySize, SMEM_SZ);

    dim3 grid(8, BATCH);

    mma_conv<1, false><<<grid, 256, SMEM_SZ>>>(x, wcv + WIN_OFF, in_b, gA);

    const float* cur = gA;
    float* nxt = gB;
    for (int l = 0; l < 20; l++) {
        mma_conv<32, true><<<grid, 256, SMEM_SZ>>>(
            cur, wcv + (size_t)l * WL_HALVES, convs_b + l * 32, nxt);
        float* tmp = (float*)cur;
        cur = nxt;
        nxt = tmp;
    }

    out1x1_kernel<<<(BATCH * 1024) / 256, 256>>>(cur, out_w, out_b, (float*)d_out);
}

// round 5
// speedup vs baseline: 4.7134x; 1.2995x over previous
#include <cuda_runtime.h>
#include <cuda_fp16.h>
#include <cstdint>

#define BATCH 16
#define HALF_OFF (BATCH * 32 * 1024)    // floats per half-buffer (524288)

// in_conv output (complete) + two ping-pong split buffers (2 halves each).
__device__ float g_in[HALF_OFF];
__device__ float g_sp0[2 * HALF_OFF];
__device__ float g_sp1[2 * HALF_OFF];

// Converted weights (fp16 hi/lo split, lo pre-scaled by 2048), k-permuted:
// hidden: [20][ci 32][ky 32][h 2][co 32][kx 32], input layer appended.
#define WL_HALVES (32 * 32 * 2 * 32 * 32)
#define WIN_OFF   (20 * WL_HALVES)
__device__ __half g_wcv[20 * WL_HALVES + 32 * 2 * 32 * 32];

// Iterated circular pad (31 iters): core [31,62]->j-31; outside: even->31, odd->0.
__device__ __forceinline__ int padidx(int j) {
    return (j >= 31 && j <= 62) ? (j - 31) : ((j & 1) ? 0 : 31);
}

// k-permutation: halves {2q,2q+1,2q+8,2q+9} contiguous (one LDS.64 -> b0,b1).
__device__ __forceinline__ int kperm(int kx) {
    return (kx & 16) + 4 * ((kx & 7) >> 1) + ((kx >> 3) & 1) * 2 + (kx & 1);
}

// ---------------- weight conversion --------------------------------------
__global__ void convert_weights(const float* __restrict__ convs_w,
                                const float* __restrict__ in_w)
{
    long long i = (long long)blockIdx.x * 256 + threadIdx.x;
    const long long NH = 20ll * 32 * 32 * 32 * 32;
    if (i < NH) {
        int kx = (int)(i & 31); long long r = i >> 5;
        int co = (int)(r & 31); r >>= 5;
        int ky = (int)(r & 31); r >>= 5;
        int ci = (int)(r & 31); r >>= 5;
        int l  = (int)r;
        float v = convs_w[((((long long)l * 32 + co) * 32 + ci) * 32 + ky) * 32 + kx];
        __half h  = __float2half_rn(v);
        __half lo = __float2half_rn((v - __half2float(h)) * 2048.0f);
        long long ob = (long long)l * WL_HALVES
                     + ((((long long)ci * 32 + ky) * 2 + 0) * 32 + co) * 32 + kperm(kx);
        g_wcv[ob] = h;
        g_wcv[ob + 32 * 32] = lo;          // h-dim stride = 1024 halves
    } else {
        long long j = i - NH;
        if (j < 32 * 32 * 32) {
            int kx = (int)(j & 31); int rr = (int)(j >> 5);
            int co = rr & 31; rr >>= 5;
            int ky = rr & 31;
            float v = in_w[(co * 32 + ky) * 32 + kx];   // [co][1][ky][kx]
            __half h  = __float2half_rn(v);
            __half lo = __float2half_rn((v - __half2float(h)) * 2048.0f);
            long long ob = WIN_OFF + (((long long)ky * 2 + 0) * 32 + co) * 32 + kperm(kx);
            g_wcv[ob] = h;
            g_wcv[ob + 32 * 32] = lo;
        }
    }
}

// ---------------- mma helper ----------------------------------------------
__device__ __forceinline__ void mma16816(float* d, const uint32_t* a,
                                         uint32_t b0, uint32_t b1) {
    asm volatile(
        "mma.sync.aligned.m16n8k16.row.col.f32.f16.f16.f32 "
        "{%0,%1,%2,%3}, {%4,%5,%6,%7}, {%8,%9}, {%0,%1,%2,%3};"
        : "+f"(d[0]), "+f"(d[1]), "+f"(d[2]), "+f"(d[3])
        : "r"(a[0]), "r"(a[1]), "r"(a[2]), "r"(a[3]), "r"(b0), "r"(b1));
}

// ---------------- smem layout (halves) -------------------------------------
#define PH_H 0                        // pad hi [46][96]
#define PL_H 4416                     // pad lo [46][96]
#define SB_H 8832                     // B stage [2 buf][4 ky][2 h][32 co][48]
#define BUF_STRIDE 12288
#define SMEM_HALVES (8832 + 2 * BUF_STRIDE)
#define SMEM_SZ (SMEM_HALVES * 2)

// One CTA: out-half kk of out[b, :, oyh*8 .. +7, :]. M=256, N=32, K=NCI_H*1024.
// Warp w owns oy row w (2 m-tiles sharing B). kk = blockIdx.z selects ci half.
// NSRC=2: input = sum of two half-buffers (+ optional ReLU) fused into pad load.
template <int NCI_H, int NSRC, bool RELU_IN>
__global__ __launch_bounds__(256, 1)
void mma_conv(const float* __restrict__ in,
              const __half* __restrict__ wv,
              const float* __restrict__ bias,
              float* __restrict__ out)
{
    extern __shared__ __half sh[];
    __half* pH = sh + PH_H;
    __half* pL = sh + PL_H;
    __half* sB = sh + SB_H;

    const int b = blockIdx.y, oyh = blockIdx.x, kk = blockIdx.z;
    const int t = threadIdx.x, lane = t & 31, wid = t >> 5;
    const int pr0 = oyh * 16;
    constexpr int NCI_TOT = (NCI_H == 1) ? 1 : 32;

    const __half* wvk = wv + (size_t)kk * NCI_H * 65536;
    float* outk = out + (size_t)kk * HALF_OFF;

    auto load_pad = [&](int ci) {
        const float* s0 = in + (b * NCI_TOT + ci) * 1024;
        for (int k = t; k < 46 * 94; k += 256) {
            int lr = k / 94, c = k - lr * 94;
            int off = padidx(pr0 + lr) * 32 + padidx(c);
            float v = s0[off];
            if (NSRC == 2) v += s0[HALF_OFF + off];
            if (RELU_IN) v = fmaxf(v, 0.0f);
            __half h = __float2half_rn(v);
            pH[lr * 96 + c] = h;
            pL[lr * 96 + c] = __float2half_rn((v - __half2float(h)) * 2048.0f);
        }
    };

    // staging: thread t owns one (ky_l, h, co) row of 32 halves (48 stride)
    const int st_ky = t >> 6, st_h = (t >> 5) & 1, st_co = t & 31;
    __half* st_dst0 = sB + ((st_ky * 2 + st_h) * 32 + st_co) * 48;

    constexpr int NCHUNK = NCI_H * 8;     // 4 ky per chunk

    uint4 pf[4];
    {
        const uint4* g = (const uint4*)wvk + t * 4;
        pf[0] = g[0]; pf[1] = g[1]; pf[2] = g[2]; pf[3] = g[3];
    }
    load_pad(kk * NCI_H);
    __syncthreads();

    float C1[32] = {}, C2a[32] = {}, C2b[32] = {};
    const int g4 = lane >> 2, q4 = lane & 3;

    for (int c = 0; c < NCHUNK; c++) {
        const int buf = c & 1;

        if (NCI_H > 1 && c > 0 && (c & 7) == 0) {
            __syncthreads();
            load_pad(kk * NCI_H + (c >> 3));
        }

        {
            uint4* d = (uint4*)(st_dst0 + buf * BUF_STRIDE);
            d[0] = pf[0]; d[1] = pf[1]; d[2] = pf[2]; d[3] = pf[3];
        }
        if (c + 1 < NCHUNK) {
            const uint4* g = (const uint4*)wvk + (c + 1) * 1024 + t * 4;
            pf[0] = g[0]; pf[1] = g[1]; pf[2] = g[2]; pf[3] = g[3];
        }
        __syncthreads();

        const int ky0 = (c & 7) * 4;
        #pragma unroll
        for (int kyl = 0; kyl < 4; kyl++) {
            const int R = 2 * wid + ky0 + kyl;
            const __half* arow = pH + R * 96;
            const __half* lrow = pL + R * 96;
            const __half* bky  = sB + buf * BUF_STRIDE + kyl * 3072
                               + g4 * 48 + q4 * 4;
            #pragma unroll
            for (int kxi = 0; kxi < 2; kxi++) {
                const int kxh  = kxi * 16;
                const int aoff = kxh + 2 * g4 + 2 * q4;
                uint32_t ah0[4], ah1[4], al0[4], al1[4];
                #pragma unroll
                for (int i = 0; i < 4; i++) {
                    const int o = aoff + 16 * (i & 1) + 8 * (i >> 1);
                    ah0[i] = *(const uint32_t*)(arow + o);
                    ah1[i] = *(const uint32_t*)(arow + o + 32);
                    al0[i] = *(const uint32_t*)(lrow + o);
                    al1[i] = *(const uint32_t*)(lrow + o + 32);
                }
                const __half* bb = bky + kxh;
                uint2 bh[4], bl[4];
                #pragma unroll
                for (int nt = 0; nt < 4; nt++) {
                    bh[nt] = *(const uint2*)(bb + nt * 384);          // h=0
                    bl[nt] = *(const uint2*)(bb + nt * 384 + 1536);   // h=1
                }
                #pragma unroll
                for (int nt = 0; nt < 4; nt++) {
                    mma16816(C1  + nt * 4,      ah0, bh[nt].x, bh[nt].y);
                    mma16816(C1  + 16 + nt * 4, ah1, bh[nt].x, bh[nt].y);
                    mma16816(C2a + nt * 4,      al0, bh[nt].x, bh[nt].y);
                    mma16816(C2a + 16 + nt * 4, al1, bh[nt].x, bh[nt].y);
                    mma16816(C2b + nt * 4,      ah0, bl[nt].x, bl[nt].y);
                    mma16816(C2b + 16 + nt * 4, ah1, bl[nt].x, bl[nt].y);
                }
            }
        }
    }

    // epilogue: raw partial sums (bias only from kk==0 half; ReLU at consumer)
    const int oy = oyh * 8 + wid;
    const float inv = 1.0f / 2048.0f;
    const float bs = (kk == 0) ? 1.0f : 0.0f;
    #pragma unroll
    for (int mt = 0; mt < 2; mt++) {
        const int oxa = mt * 16 + g4, oxb = oxa + 8;
        #pragma unroll
        for (int nt = 0; nt < 4; nt++) {
            const int co = nt * 8 + q4 * 2;
            const int ix = mt * 16 + nt * 4;
            const float b0v = bias[co] * bs, b1v = bias[co + 1] * bs;
            float v00 = C1[ix+0] + (C2a[ix+0] + C2b[ix+0]) * inv + b0v;
            float v01 = C1[ix+1] + (C2a[ix+1] + C2b[ix+1]) * inv + b1v;
            float v10 = C1[ix+2] + (C2a[ix+2] + C2b[ix+2]) * inv + b0v;
            float v11 = C1[ix+3] + (C2a[ix+3] + C2b[ix+3]) * inv + b1v;
            outk[((b * 32 + co    ) * 32 + oy) * 32 + oxa] = v00;
            outk[((b * 32 + co + 1) * 32 + oy) * 32 + oxa] = v01;
            outk[((b * 32 + co    ) * 32 + oy) * 32 + oxb] = v10;
            outk[((b * 32 + co + 1) * 32 + oy) * 32 + oxb] = v11;
        }
    }
}

// Final 1x1 conv over split input (sum halves + ReLU fused)
__global__ void out1x1_kernel(const float* __restrict__ h,
                              const float* __restrict__ ow,
                              const float* __restrict__ ob,
                              float* __restrict__ out)
{
    const int i = blockIdx.x * blockDim.x + threadIdx.x;
    if (i >= BATCH * 1024) return;
    const int b = i >> 10;
    const int p = i & 1023;
    const float* hp = h + b * 32 * 1024 + p;
    float acc = ob[0];
    #pragma unroll
    for (int co = 0; co < 32; co++) {
        float v = fmaxf(hp[co * 1024] + hp[HALF_OFF + co * 1024], 0.0f);
        acc = fmaf(v, __ldg(ow + co), acc);
    }
    out[i] = acc;
}

extern "C" void kernel_launch(void* const* d_in, const int* in_sizes, int n_in,
                              void* d_out, int out_size)
{
    const float* x       = (const float*)d_in[0];
    const float* in_w    = (const float*)d_in[1];
    const float* in_b    = (const float*)d_in[2];
    const float* convs_w = (const float*)d_in[3];
    const float* convs_b = (const float*)d_in[4];
    const float* out_w   = (const float*)d_in[5];
    const float* out_b   = (const float*)d_in[6];

    float *gin = nullptr, *gs0 = nullptr, *gs1 = nullptr;
    __half* wcv = nullptr;
    cudaGetSymbolAddress((void**)&gin, g_in);
    cudaGetSymbolAddress((void**)&gs0, g_sp0);
    cudaGetSymbolAddress((void**)&gs1, g_sp1);
    cudaGetSymbolAddress((void**)&wcv, g_wcv);

    const long long total = 20ll * 32 * 32 * 32 * 32 + 32 * 32 * 32;
    convert_weights<<<(int)((total + 255) / 256), 256>>>(convs_w, in_w);

    cudaFuncSetAttribute(mma_conv<1, 1, false>,
                         cudaFuncAttributeMaxDynamicSharedMemorySize, SMEM_SZ);
    cudaFuncSetAttribute(mma_conv<16, 1, false>,
                         cudaFuncAttributeMaxDynamicSharedMemorySize, SMEM_SZ);
    cudaFuncSetAttribute(mma_conv<16, 2, true>,
                         cudaFuncAttributeMaxDynamicSharedMemorySize, SMEM_SZ);

    // in_conv: complete (unsplit) output, no ReLU anywhere around it
    mma_conv<1, 1, false><<<dim3(4, BATCH, 1), 256, SMEM_SZ>>>(
        x, wcv + WIN_OFF, in_b, gin);

    // hidden layer 0: reads unsplit g_in (no input ReLU), writes split g_sp0
    mma_conv<16, 1, false><<<dim3(4, BATCH, 2), 256, SMEM_SZ>>>(
        gin, wcv, convs_b, gs0);

    // hidden layers 1..19: read split (sum+ReLU fused), write split
    float* cur = gs0;
    float* nxt = gs1;
    for (int l = 1; l < 20; l++) {
        mma_conv<16, 2, true><<<dim3(4, BATCH, 2), 256, SMEM_SZ>>>(
            cur, wcv + (size_t)l * WL_HALVES, convs_b + l * 32, nxt);
        float* tmp = cur; cur = nxt; nxt = tmp;
    }

    // 1x1 output conv (sum halves + ReLU fused)
    out1x1_kernel<<<(BATCH * 1024) / 256, 256>>>(cur, out_w, out_b, (float*)d_out);
}

// round 6
// speedup vs baseline: 4.7962x; 1.0176x over previous
#include <cuda_runtime.h>
#include <cuda_fp16.h>
#include <cstdint>

#define BATCH 16
#define HALF_OFF (BATCH * 32 * 1024)    // floats per half-buffer (524288)

// in_conv output (complete) + two ping-pong split buffers (2 halves each).
__device__ float g_in[HALF_OFF];
__device__ float g_sp0[2 * HALF_OFF];
__device__ float g_sp1[2 * HALF_OFF];

// Converted weights (fp16 hi/lo split, lo pre-scaled by 2048), k-permuted:
// hidden: [20][ci 32][ky 32][h 2][co 32][kx 32], input layer appended.
#define WL_HALVES (32 * 32 * 2 * 32 * 32)
#define WIN_OFF   (20 * WL_HALVES)
__device__ __half g_wcv[20 * WL_HALVES + 32 * 2 * 32 * 32];

// Iterated circular pad (31 iters): core [31,62]->j-31; outside: even->31, odd->0.
__device__ __forceinline__ int padidx(int j) {
    return (j >= 31 && j <= 62) ? (j - 31) : ((j & 1) ? 0 : 31);
}

// k-permutation: halves {2q,2q+1,2q+8,2q+9} contiguous (one LDS.64 -> b0,b1).
__device__ __forceinline__ int kperm(int kx) {
    return (kx & 16) + 4 * ((kx & 7) >> 1) + ((kx >> 3) & 1) * 2 + (kx & 1);
}

// ---------------- weight conversion --------------------------------------
__global__ void convert_weights(const float* __restrict__ convs_w,
                                const float* __restrict__ in_w)
{
    long long i = (long long)blockIdx.x * 256 + threadIdx.x;
    const long long NH = 20ll * 32 * 32 * 32 * 32;
    if (i < NH) {
        int kx = (int)(i & 31); long long r = i >> 5;
        int co = (int)(r & 31); r >>= 5;
        int ky = (int)(r & 31); r >>= 5;
        int ci = (int)(r & 31); r >>= 5;
        int l  = (int)r;
        float v = convs_w[((((long long)l * 32 + co) * 32 + ci) * 32 + ky) * 32 + kx];
        __half h  = __float2half_rn(v);
        __half lo = __float2half_rn((v - __half2float(h)) * 2048.0f);
        long long ob = (long long)l * WL_HALVES
                     + ((((long long)ci * 32 + ky) * 2 + 0) * 32 + co) * 32 + kperm(kx);
        g_wcv[ob] = h;
        g_wcv[ob + 32 * 32] = lo;          // h-dim stride = 1024 halves
    } else {
        long long j = i - NH;
        if (j < 32 * 32 * 32) {
            int kx = (int)(j & 31); int rr = (int)(j >> 5);
            int co = rr & 31; rr >>= 5;
            int ky = rr & 31;
            float v = in_w[(co * 32 + ky) * 32 + kx];   // [co][1][ky][kx]
            __half h  = __float2half_rn(v);
            __half lo = __float2half_rn((v - __half2float(h)) * 2048.0f);
            long long ob = WIN_OFF + (((long long)ky * 2 + 0) * 32 + co) * 32 + kperm(kx);
            g_wcv[ob] = h;
            g_wcv[ob + 32 * 32] = lo;
        }
    }
}

// ---------------- mma helper ----------------------------------------------
__device__ __forceinline__ void mma16816(float* d, const uint32_t* a,
                                         uint32_t b0, uint32_t b1) {
    asm volatile(
        "mma.sync.aligned.m16n8k16.row.col.f32.f16.f16.f32 "
        "{%0,%1,%2,%3}, {%4,%5,%6,%7}, {%8,%9}, {%0,%1,%2,%3};"
        : "+f"(d[0]), "+f"(d[1]), "+f"(d[2]), "+f"(d[3])
        : "r"(a[0]), "r"(a[1]), "r"(a[2]), "r"(a[3]), "r"(b0), "r"(b1));
}

// ---------------- smem layout (halves) -------------------------------------
#define PH_H 0                        // pad hi [46][96]
#define PL_H 4416                     // pad lo [46][96]
#define SB_H 8832                     // B stage [2 buf][4 ky][2 h][32 co][48]
#define BUF_STRIDE 12288
#define SMEM_HALVES (8832 + 2 * BUF_STRIDE)
#define SMEM_SZ (SMEM_HALVES * 2)

// Load fragments for k-step S (kyl = S>>1, kxi = S&1) of chunk with base ky0.
#define LOADF(ah0_, ah1_, al0_, al1_, bh_, bl_, S) do {                        \
    const int kyl_ = (S) >> 1, kxi_ = (S) & 1;                                  \
    const int R_ = 2 * wid + ky0 + kyl_;                                        \
    const __half* arow_ = pH + R_ * 96;                                         \
    const __half* lrow_ = pL + R_ * 96;                                         \
    const int kxh_ = kxi_ * 16;                                                 \
    const int aoff_ = kxh_ + 2 * g4 + 2 * q4;                                   \
    _Pragma("unroll")                                                           \
    for (int i_ = 0; i_ < 4; i_++) {                                            \
        const int o_ = aoff_ + 16 * (i_ & 1) + 8 * (i_ >> 1);                   \
        ah0_[i_] = *(const uint32_t*)(arow_ + o_);                              \
        ah1_[i_] = *(const uint32_t*)(arow_ + o_ + 32);                         \
        al0_[i_] = *(const uint32_t*)(lrow_ + o_);                              \
        al1_[i_] = *(const uint32_t*)(lrow_ + o_ + 32);                         \
    }                                                                           \
    const __half* bb_ = sB + buf * BUF_STRIDE + kyl_ * 3072                     \
                      + g4 * 48 + q4 * 4 + kxh_;                                \
    _Pragma("unroll")                                                           \
    for (int nt_ = 0; nt_ < 4; nt_++) {                                         \
        bh_[nt_] = *(const uint2*)(bb_ + nt_ * 384);                            \
        bl_[nt_] = *(const uint2*)(bb_ + nt_ * 384 + 1536);                     \
    }                                                                           \
} while (0)

// 24 MMAs; same-accumulator writes are >= 8 issues apart (no exposed RAW).
#define MMAB(ah0_, ah1_, al0_, al1_, bh_, bl_) do {                             \
    _Pragma("unroll")                                                           \
    for (int nt_ = 0; nt_ < 4; nt_++)                                           \
        mma16816(C1 + nt_ * 4, ah0_, bh_[nt_].x, bh_[nt_].y);                   \
    _Pragma("unroll")                                                           \
    for (int nt_ = 0; nt_ < 4; nt_++)                                           \
        mma16816(C1 + 16 + nt_ * 4, ah1_, bh_[nt_].x, bh_[nt_].y);              \
    _Pragma("unroll")                                                           \
    for (int nt_ = 0; nt_ < 4; nt_++)                                           \
        mma16816(C2 + nt_ * 4, al0_, bh_[nt_].x, bh_[nt_].y);                   \
    _Pragma("unroll")                                                           \
    for (int nt_ = 0; nt_ < 4; nt_++)                                           \
        mma16816(C2 + 16 + nt_ * 4, al1_, bh_[nt_].x, bh_[nt_].y);              \
    _Pragma("unroll")                                                           \
    for (int nt_ = 0; nt_ < 4; nt_++)                                           \
        mma16816(C2 + nt_ * 4, ah0_, bl_[nt_].x, bl_[nt_].y);                   \
    _Pragma("unroll")                                                           \
    for (int nt_ = 0; nt_ < 4; nt_++)                                           \
        mma16816(C2 + 16 + nt_ * 4, ah1_, bl_[nt_].x, bl_[nt_].y);              \
} while (0)

// One CTA: out-half kk of out[b, :, oyh*8 .. +7, :]. M=256, N=32, K=NCI_H*1024.
// Warp w owns oy row w (2 m-tiles sharing B). kk = blockIdx.z selects ci half.
template <int NCI_H, int NSRC, bool RELU_IN>
__global__ __launch_bounds__(256, 1)
void mma_conv(const float* __restrict__ in,
              const __half* __restrict__ wv,
              const float* __restrict__ bias,
              float* __restrict__ out)
{
    extern __shared__ __half sh[];
    __half* pH = sh + PH_H;
    __half* pL = sh + PL_H;
    __half* sB = sh + SB_H;

    const int b = blockIdx.y, oyh = blockIdx.x, kk = blockIdx.z;
    const int t = threadIdx.x, lane = t & 31, wid = t >> 5;
    const int pr0 = oyh * 16;
    constexpr int NCI_TOT = (NCI_H == 1) ? 1 : 32;

    const __half* wvk = wv + (size_t)kk * NCI_H * 65536;
    float* outk = out + (size_t)kk * HALF_OFF;

    auto load_pad = [&](int ci) {
        const float* s0 = in + (b * NCI_TOT + ci) * 1024;
        for (int k = t; k < 46 * 94; k += 256) {
            int lr = k / 94, c = k - lr * 94;
            int off = padidx(pr0 + lr) * 32 + padidx(c);
            float v = s0[off];
            if (NSRC == 2) v += s0[HALF_OFF + off];
            if (RELU_IN) v = fmaxf(v, 0.0f);
            __half h = __float2half_rn(v);
            pH[lr * 96 + c] = h;
            pL[lr * 96 + c] = __float2half_rn((v - __half2float(h)) * 2048.0f);
        }
    };

    // staging: thread t owns one (ky_l, h, co) row of 32 halves (48 stride)
    const int st_ky = t >> 6, st_h = (t >> 5) & 1, st_co = t & 31;
    __half* st_dst0 = sB + ((st_ky * 2 + st_h) * 32 + st_co) * 48;

    constexpr int NCHUNK = NCI_H * 8;     // 4 ky per chunk

    uint4 pf[4];
    {
        const uint4* g = (const uint4*)wvk + t * 4;
        pf[0] = g[0]; pf[1] = g[1]; pf[2] = g[2]; pf[3] = g[3];
    }
    load_pad(kk * NCI_H);
    __syncthreads();

    float C1[32] = {}, C2[32] = {};
    const int g4 = lane >> 2, q4 = lane & 3;

    for (int c = 0; c < NCHUNK; c++) {
        const int buf = c & 1;

        if (NCI_H > 1 && c > 0 && (c & 7) == 0) {
            __syncthreads();
            load_pad(kk * NCI_H + (c >> 3));
        }

        {
            uint4* d = (uint4*)(st_dst0 + buf * BUF_STRIDE);
            d[0] = pf[0]; d[1] = pf[1]; d[2] = pf[2]; d[3] = pf[3];
        }
        if (c + 1 < NCHUNK) {
            const uint4* g = (const uint4*)wvk + (c + 1) * 1024 + t * 4;
            pf[0] = g[0]; pf[1] = g[1]; pf[2] = g[2]; pf[3] = g[3];
        }
        __syncthreads();

        const int ky0 = (c & 7) * 4;

        // software-pipelined 8 k-steps: frags(s+1) loaded before MMAs(s)
        uint32_t Aah0[4], Aah1[4], Aal0[4], Aal1[4];
        uint32_t Bah0[4], Bah1[4], Bal0[4], Bal1[4];
        uint2 Abh[4], Abl[4], Bbh[4], Bbl[4];

        LOADF(Aah0, Aah1, Aal0, Aal1, Abh, Abl, 0);
        #pragma unroll
        for (int s = 0; s < 8; s++) {
            if ((s & 1) == 0) {
                if (s + 1 < 8) LOADF(Bah0, Bah1, Bal0, Bal1, Bbh, Bbl, s + 1);
                MMAB(Aah0, Aah1, Aal0, Aal1, Abh, Abl);
            } else {
                if (s + 1 < 8) LOADF(Aah0, Aah1, Aal0, Aal1, Abh, Abl, s + 1);
                MMAB(Bah0, Bah1, Bal0, Bal1, Bbh, Bbl);
            }
        }
    }

    // epilogue: raw partial sums (bias only from kk==0 half; ReLU at consumer)
    const int oy = oyh * 8 + wid;
    const float inv = 1.0f / 2048.0f;
    const float bs = (kk == 0) ? 1.0f : 0.0f;
    #pragma unroll
    for (int mt = 0; mt < 2; mt++) {
        const int oxa = mt * 16 + g4, oxb = oxa + 8;
        #pragma unroll
        for (int nt = 0; nt < 4; nt++) {
            const int co = nt * 8 + q4 * 2;
            const int ix = mt * 16 + nt * 4;
            const float b0v = bias[co] * bs, b1v = bias[co + 1] * bs;
            float v00 = C1[ix+0] + C2[ix+0] * inv + b0v;
            float v01 = C1[ix+1] + C2[ix+1] * inv + b1v;
            float v10 = C1[ix+2] + C2[ix+2] * inv + b0v;
            float v11 = C1[ix+3] + C2[ix+3] * inv + b1v;
            outk[((b * 32 + co    ) * 32 + oy) * 32 + oxa] = v00;
            outk[((b * 32 + co + 1) * 32 + oy) * 32 + oxa] = v01;
            outk[((b * 32 + co    ) * 32 + oy) * 32 + oxb] = v10;
            outk[((b * 32 + co + 1) * 32 + oy) * 32 + oxb] = v11;
        }
    }
}

// Final 1x1 conv over split input (sum halves + ReLU fused)
__global__ void out1x1_kernel(const float* __restrict__ h,
                              const float* __restrict__ ow,
                              const float* __restrict__ ob,
                              float* __restrict__ out)
{
    const int i = blockIdx.x * blockDim.x + threadIdx.x;
    if (i >= BATCH * 1024) return;
    const int b = i >> 10;
    const int p = i & 1023;
    const float* hp = h + b * 32 * 1024 + p;
    float acc = ob[0];
    #pragma unroll
    for (int co = 0; co < 32; co++) {
        float v = fmaxf(hp[co * 1024] + hp[HALF_OFF + co * 1024], 0.0f);
        acc = fmaf(v, __ldg(ow + co), acc);
    }
    out[i] = acc;
}

extern "C" void kernel_launch(void* const* d_in, const int* in_sizes, int n_in,
                              void* d_out, int out_size)
{
    const float* x       = (const float*)d_in[0];
    const float* in_w    = (const float*)d_in[1];
    const float* in_b    = (const float*)d_in[2];
    const float* convs_w = (const float*)d_in[3];
    const float* convs_b = (const float*)d_in[4];
    const float* out_w   = (const float*)d_in[5];
    const float* out_b   = (const float*)d_in[6];

    float *gin = nullptr, *gs0 = nullptr, *gs1 = nullptr;
    __half* wcv = nullptr;
    cudaGetSymbolAddress((void**)&gin, g_in);
    cudaGetSymbolAddress((void**)&gs0, g_sp0);
    cudaGetSymbolAddress((void**)&gs1, g_sp1);
    cudaGetSymbolAddress((void**)&wcv, g_wcv);

    const long long total = 20ll * 32 * 32 * 32 * 32 + 32 * 32 * 32;
    convert_weights<<<(int)((total + 255) / 256), 256>>>(convs_w, in_w);

    cudaFuncSetAttribute(mma_conv<1, 1, false>,
                         cudaFuncAttributeMaxDynamicSharedMemorySize, SMEM_SZ);
    cudaFuncSetAttribute(mma_conv<16, 1, false>,
                         cudaFuncAttributeMaxDynamicSharedMemorySize, SMEM_SZ);
    cudaFuncSetAttribute(mma_conv<16, 2, true>,
                         cudaFuncAttributeMaxDynamicSharedMemorySize, SMEM_SZ);

    // in_conv: complete (unsplit) output, no ReLU anywhere around it
    mma_conv<1, 1, false><<<dim3(4, BATCH, 1), 256, SMEM_SZ>>>(
        x, wcv + WIN_OFF, in_b, gin);

    // hidden layer 0: reads unsplit g_in (no input ReLU), writes split g_sp0
    mma_conv<16, 1, false><<<dim3(4, BATCH, 2), 256, SMEM_SZ>>>(
        gin, wcv, convs_b, gs0);

    // hidden layers 1..19: read split (sum+ReLU fused), write split
    float* cur = gs0;
    float* nxt = gs1;
    for (int l = 1; l < 20; l++) {
        mma_conv<16, 2, true><<<dim3(4, BATCH, 2), 256, SMEM_SZ>>>(
            cur, wcv + (size_t)l * WL_HALVES, convs_b + l * 32, nxt);
        float* tmp = cur; cur = nxt; nxt = tmp;
    }

    // 1x1 output conv (sum halves + ReLU fused)
    out1x1_kernel<<<(BATCH * 1024) / 256, 256>>>(cur, out_w, out_b, (float*)d_out);
}